// round 1
// baseline (speedup 1.0000x reference)
#include <cuda_runtime.h>
#include <math.h>

// Problem constants
#define BATCH 8192
#define EDIM  256
#define HDIM  50
#define N_INNER 31
#define N_LEAF  32

// Scratch (device globals; no allocation allowed)
__device__ float g_emb0[BATCH * EDIM];
__device__ float g_emb1[BATCH * EDIM];
__device__ float g_pR[N_INNER * BATCH];
__device__ float g_yleaf[N_LEAF * BATCH];

// ---------------------------------------------------------------------------
// Encoder GEMM: C[8192,256] = relu(A[8192,256] @ W[256,256] + bias[256])
// 128x128 tile, BK=16, 256 threads, 8x8 per thread.
// ---------------------------------------------------------------------------
__global__ __launch_bounds__(256) void gemm_relu_kernel(
    const float* __restrict__ A, const float* __restrict__ W,
    const float* __restrict__ bias, float* __restrict__ C)
{
    __shared__ float As[16][132];
    __shared__ float Ws[16][128];

    const int m0 = (blockIdx.x >> 1) * 128;
    const int n0 = (blockIdx.x & 1) * 128;
    const int t  = threadIdx.x;
    const int tx = t & 15;   // col group -> cols tx*8
    const int ty = t >> 4;   // row group -> rows ty*8

    float acc[8][8];
#pragma unroll
    for (int i = 0; i < 8; i++)
#pragma unroll
        for (int j = 0; j < 8; j++) acc[i][j] = 0.f;

    const int lm  = t >> 2;          // 0..63
    const int lkv = (t & 3) * 4;     // 0,4,8,12
    const int wr  = t >> 5;          // 0..7
    const int wc  = (t & 31) * 4;    // 0..124

    for (int k0 = 0; k0 < 256; k0 += 16) {
        // A tile 128x16 (transposed into smem)
        float4 a0 = *(const float4*)&A[(size_t)(m0 + lm) * 256 + k0 + lkv];
        float4 a1 = *(const float4*)&A[(size_t)(m0 + lm + 64) * 256 + k0 + lkv];
        As[lkv + 0][lm] = a0.x; As[lkv + 1][lm] = a0.y;
        As[lkv + 2][lm] = a0.z; As[lkv + 3][lm] = a0.w;
        As[lkv + 0][lm + 64] = a1.x; As[lkv + 1][lm + 64] = a1.y;
        As[lkv + 2][lm + 64] = a1.z; As[lkv + 3][lm + 64] = a1.w;
        // W tile 16x128
        *(float4*)&Ws[wr][wc]     = *(const float4*)&W[(size_t)(k0 + wr) * 256 + n0 + wc];
        *(float4*)&Ws[wr + 8][wc] = *(const float4*)&W[(size_t)(k0 + wr + 8) * 256 + n0 + wc];
        __syncthreads();

#pragma unroll
        for (int k = 0; k < 16; k++) {
            float a[8], b[8];
#pragma unroll
            for (int i = 0; i < 8; i++) a[i] = As[k][ty * 8 + i];
#pragma unroll
            for (int j = 0; j < 8; j++) b[j] = Ws[k][tx * 8 + j];
#pragma unroll
            for (int i = 0; i < 8; i++)
#pragma unroll
                for (int j = 0; j < 8; j++) acc[i][j] = fmaf(a[i], b[j], acc[i][j]);
        }
        __syncthreads();
    }

    float bn[8];
#pragma unroll
    for (int j = 0; j < 8; j++) bn[j] = bias[n0 + tx * 8 + j];

#pragma unroll
    for (int i = 0; i < 8; i++) {
        float4 o0, o1;
        o0.x = fmaxf(acc[i][0] + bn[0], 0.f);
        o0.y = fmaxf(acc[i][1] + bn[1], 0.f);
        o0.z = fmaxf(acc[i][2] + bn[2], 0.f);
        o0.w = fmaxf(acc[i][3] + bn[3], 0.f);
        o1.x = fmaxf(acc[i][4] + bn[4], 0.f);
        o1.y = fmaxf(acc[i][5] + bn[5], 0.f);
        o1.z = fmaxf(acc[i][6] + bn[6], 0.f);
        o1.w = fmaxf(acc[i][7] + bn[7], 0.f);
        float* dst = &C[(size_t)(m0 + ty * 8 + i) * 256 + n0 + tx * 8];
        *(float4*)dst = o0;
        *(float4*)(dst + 4) = o1;
    }
}

// ---------------------------------------------------------------------------
// Leaf kernel: per (leaf, 64-row tile)
//   hl = relu(emb @ W1[l] + b1[l])   [64, 256]
//   y  = hl @ W2[l] + b2[l]          [64]
// GEMM tile 64x256, BK=16, 256 threads, 8x8 per thread; epilogue reduces
// relu(acc)+bias dotted with W2 across the warp (one warp owns 8 rows).
// ---------------------------------------------------------------------------
__global__ __launch_bounds__(256) void leaf_kernel(
    const float* __restrict__ emb, const float* __restrict__ W1,
    const float* __restrict__ b1, const float* __restrict__ W2,
    const float* __restrict__ b2, float* __restrict__ yleaf)
{
    __shared__ float As[16][68];
    __shared__ float Ws[16][256];

    const int l  = blockIdx.y;
    const int m0 = blockIdx.x * 64;
    const float* Wl = W1 + (size_t)l * 256 * 256;

    const int t  = threadIdx.x;
    const int tx = t & 31;   // lane: cols tx*8
    const int ty = t >> 5;   // warp: rows ty*8

    float acc[8][8];
#pragma unroll
    for (int i = 0; i < 8; i++)
#pragma unroll
        for (int j = 0; j < 8; j++) acc[i][j] = 0.f;

    const int lm  = t >> 2;
    const int lkv = (t & 3) * 4;
    const int wr  = t >> 4;          // 0..15
    const int wc  = (t & 15) * 16;   // 0..240

    for (int k0 = 0; k0 < 256; k0 += 16) {
        float4 a0 = *(const float4*)&emb[(size_t)(m0 + lm) * 256 + k0 + lkv];
        As[lkv + 0][lm] = a0.x; As[lkv + 1][lm] = a0.y;
        As[lkv + 2][lm] = a0.z; As[lkv + 3][lm] = a0.w;

        const float* src = &Wl[(size_t)(k0 + wr) * 256 + wc];
        *(float4*)&Ws[wr][wc + 0]  = *(const float4*)&src[0];
        *(float4*)&Ws[wr][wc + 4]  = *(const float4*)&src[4];
        *(float4*)&Ws[wr][wc + 8]  = *(const float4*)&src[8];
        *(float4*)&Ws[wr][wc + 12] = *(const float4*)&src[12];
        __syncthreads();

#pragma unroll
        for (int k = 0; k < 16; k++) {
            float a[8], b[8];
#pragma unroll
            for (int i = 0; i < 8; i++) a[i] = As[k][ty * 8 + i];
#pragma unroll
            for (int j = 0; j < 8; j++) b[j] = Ws[k][tx * 8 + j];
#pragma unroll
            for (int i = 0; i < 8; i++)
#pragma unroll
                for (int j = 0; j < 8; j++) acc[i][j] = fmaf(a[i], b[j], acc[i][j]);
        }
        __syncthreads();
    }

    float w2[8], bb[8];
#pragma unroll
    for (int j = 0; j < 8; j++) {
        int c = tx * 8 + j;
        bb[j] = b1[l * 256 + c];
        w2[j] = W2[l * 256 + c];
    }

    float part[8];
#pragma unroll
    for (int i = 0; i < 8; i++) {
        float s = 0.f;
#pragma unroll
        for (int j = 0; j < 8; j++)
            s = fmaf(fmaxf(acc[i][j] + bb[j], 0.f), w2[j], s);
        part[i] = s;
    }

#pragma unroll
    for (int off = 16; off; off >>= 1)
#pragma unroll
        for (int i = 0; i < 8; i++)
            part[i] += __shfl_down_sync(0xffffffffu, part[i], off);

    if (tx == 0) {
        float bl = b2[l];
#pragma unroll
        for (int i = 0; i < 8; i++)
            yleaf[(size_t)l * BATCH + m0 + ty * 8 + i] = part[i] + bl;
    }
}

// ---------------------------------------------------------------------------
// Inner-node kernel: per (node, 64-row tile)
// Phase A: h = relu(emb @ W1[n] + b1[n])  [64, 50] -> smem
// Phase B: z = h @ Ww[n] + bw[n] (256 wide), softmax, dot with x,
//          b/beta dots, pR = sigmoid(beta*(w.x + b))
// ---------------------------------------------------------------------------
#define INNER_SMEM_FLOATS (16*68 + 16*64 + 64*65 + 50*256)

__global__ __launch_bounds__(256) void inner_kernel(
    const float* __restrict__ emb, const float* __restrict__ x,
    const float* __restrict__ W1, const float* __restrict__ b1,
    const float* __restrict__ Ww, const float* __restrict__ bw,
    const float* __restrict__ Wb, const float* __restrict__ bbias,
    const float* __restrict__ Wbeta, const float* __restrict__ bbeta,
    float* __restrict__ pR)
{
    extern __shared__ float sm[];
    float* As  = sm;                        // [16][68]
    float* W1s = sm + 16 * 68;              // [16][64] (cols >=50 zero)
    float* Hs  = sm + 16 * 68 + 16 * 64;    // [64][65]
    float* Wws = Hs + 64 * 65;              // [50][256] flat

    const int n  = blockIdx.y;
    const int m0 = blockIdx.x * 64;
    const int t  = threadIdx.x;

    // Preload Ww[n] (50x256) into smem
    {
        const float* src = Ww + (size_t)n * HDIM * 256;
        for (int i = t; i < (HDIM * 256) / 4; i += 256)
            *(float4*)&Wws[i * 4] = *(const float4*)&src[i * 4];
    }

    // ---- Phase A: h = relu(emb @ W1 + b1) ----
    const int rg = t & 15;   // rows rg*4+i
    const int cg = t >> 4;   // cols cg*4+q (0..63, zero-padded past 50)
    float acc[4][4];
#pragma unroll
    for (int i = 0; i < 4; i++)
#pragma unroll
        for (int q = 0; q < 4; q++) acc[i][q] = 0.f;

    const int lm  = t >> 2;
    const int lkv = (t & 3) * 4;
    const int w1k = t >> 4;        // 0..15
    const int w1j = (t & 15) * 4;  // 0..60

    for (int k0 = 0; k0 < 256; k0 += 16) {
        float4 a0 = *(const float4*)&emb[(size_t)(m0 + lm) * 256 + k0 + lkv];
        As[(lkv + 0) * 68 + lm] = a0.x; As[(lkv + 1) * 68 + lm] = a0.y;
        As[(lkv + 2) * 68 + lm] = a0.z; As[(lkv + 3) * 68 + lm] = a0.w;
#pragma unroll
        for (int u = 0; u < 4; u++) {
            int j = w1j + u;
            W1s[w1k * 64 + j] = (j < HDIM)
                ? W1[((size_t)n * 256 + k0 + w1k) * HDIM + j] : 0.f;
        }
        __syncthreads();
#pragma unroll
        for (int k = 0; k < 16; k++) {
            float a[4], w[4];
#pragma unroll
            for (int i = 0; i < 4; i++) a[i] = As[k * 68 + rg * 4 + i];
#pragma unroll
            for (int q = 0; q < 4; q++) w[q] = W1s[k * 64 + cg * 4 + q];
#pragma unroll
            for (int i = 0; i < 4; i++)
#pragma unroll
                for (int q = 0; q < 4; q++) acc[i][q] = fmaf(a[i], w[q], acc[i][q]);
        }
        __syncthreads();
    }
#pragma unroll
    for (int i = 0; i < 4; i++)
#pragma unroll
        for (int q = 0; q < 4; q++) {
            int c = cg * 4 + q;
            float v = acc[i][q] + ((c < HDIM) ? b1[n * HDIM + c] : 0.f);
            Hs[(rg * 4 + i) * 65 + c] = fmaxf(v, 0.f);
        }
    __syncthreads();

    // ---- Phase B: gates ----
    const int lane = t & 31;
    const int wrp  = t >> 5;

    float bwv[8];
#pragma unroll
    for (int u = 0; u < 8; u++) bwv[u] = bw[n * 256 + lane + 32 * u];

    const float wbb   = bbias[n];
    const float wbetb = bbeta[n];

#pragma unroll
    for (int g = 0; g < 2; g++) {
        const int r0 = wrp * 8 + g * 4;
        float z[4][8];
#pragma unroll
        for (int rr = 0; rr < 4; rr++)
#pragma unroll
            for (int u = 0; u < 8; u++) z[rr][u] = bwv[u];

        for (int j = 0; j < HDIM; j++) {
            float h0 = Hs[(r0 + 0) * 65 + j];
            float h1 = Hs[(r0 + 1) * 65 + j];
            float h2 = Hs[(r0 + 2) * 65 + j];
            float h3 = Hs[(r0 + 3) * 65 + j];
#pragma unroll
            for (int u = 0; u < 8; u++) {
                float wv = Wws[j * 256 + lane + 32 * u];
                z[0][u] = fmaf(h0, wv, z[0][u]);
                z[1][u] = fmaf(h1, wv, z[1][u]);
                z[2][u] = fmaf(h2, wv, z[2][u]);
                z[3][u] = fmaf(h3, wv, z[3][u]);
            }
        }

#pragma unroll
        for (int rr = 0; rr < 4; rr++) {
            const int r = r0 + rr;
            float mx = z[rr][0];
#pragma unroll
            for (int u = 1; u < 8; u++) mx = fmaxf(mx, z[rr][u]);
#pragma unroll
            for (int off = 16; off; off >>= 1)
                mx = fmaxf(mx, __shfl_xor_sync(0xffffffffu, mx, off));

            float se = 0.f, sx = 0.f;
            const float* xr = x + (size_t)(m0 + r) * 256;
#pragma unroll
            for (int u = 0; u < 8; u++) {
                float e = expf(z[rr][u] - mx);
                se += e;
                sx = fmaf(e, xr[lane + 32 * u], sx);
            }
            float pb = 0.f, pbt = 0.f;
            for (int j = lane; j < HDIM; j += 32) {
                float hv = Hs[r * 65 + j];
                pb  = fmaf(hv, Wb[n * HDIM + j], pb);
                pbt = fmaf(hv, Wbeta[n * HDIM + j], pbt);
            }
#pragma unroll
            for (int off = 16; off; off >>= 1) {
                se  += __shfl_xor_sync(0xffffffffu, se, off);
                sx  += __shfl_xor_sync(0xffffffffu, sx, off);
                pb  += __shfl_xor_sync(0xffffffffu, pb, off);
                pbt += __shfl_xor_sync(0xffffffffu, pbt, off);
            }
            if (lane == 0) {
                float bv   = pb + wbb;
                float beta = pbt + wbetb;
                float val  = beta * (sx / se + bv);
                pR[(size_t)n * BATCH + m0 + r] = 1.0f / (1.0f + expf(-val));
            }
        }
    }
}

// ---------------------------------------------------------------------------
// Combine: out[b] = sum_leaf prob(leaf,b) * y_leaf[leaf,b]
// ---------------------------------------------------------------------------
__global__ __launch_bounds__(256) void combine_kernel(
    const float* __restrict__ pR, const float* __restrict__ yl,
    float* __restrict__ out)
{
    const int b = blockIdx.x * 256 + threadIdx.x;
    float p[N_INNER];
#pragma unroll
    for (int i = 0; i < N_INNER; i++) p[i] = pR[(size_t)i * BATCH + b];

    float prob[N_LEAF];
    prob[0] = 1.f;
#pragma unroll
    for (int lev = 0; lev < 5; lev++) {
        const int cnt = 1 << lev;
        const int off = cnt - 1;
#pragma unroll
        for (int i = N_LEAF - 1; i >= 0; i--) {   // static bound; guard inside
            if (i < cnt) {
                float pr   = p[off + i];
                float base = prob[i];
                prob[2 * i]     = base * (1.f - pr);
                prob[2 * i + 1] = base * pr;
            }
        }
    }
    float acc = 0.f;
#pragma unroll
    for (int l = 0; l < N_LEAF; l++)
        acc = fmaf(prob[l], yl[(size_t)l * BATCH + b], acc);
    out[b] = acc;
}

// ---------------------------------------------------------------------------
extern "C" void kernel_launch(void* const* d_in, const int* in_sizes, int n_in,
                              void* d_out, int out_size)
{
    const float* x       = (const float*)d_in[0];
    const float* enc_W   = (const float*)d_in[1];
    const float* enc_b   = (const float*)d_in[2];
    const float* in_W1   = (const float*)d_in[3];
    const float* in_b1   = (const float*)d_in[4];
    const float* in_Ww   = (const float*)d_in[5];
    const float* in_bw   = (const float*)d_in[6];
    const float* in_Wb   = (const float*)d_in[7];
    const float* in_bb   = (const float*)d_in[8];
    const float* in_Wbt  = (const float*)d_in[9];
    const float* in_bbt  = (const float*)d_in[10];
    const float* lf_W1   = (const float*)d_in[11];
    const float* lf_b1   = (const float*)d_in[12];
    const float* lf_W2   = (const float*)d_in[13];
    const float* lf_b2   = (const float*)d_in[14];
    float* out = (float*)d_out;

    float *emb0, *emb1, *pR, *yl;
    cudaGetSymbolAddress((void**)&emb0, g_emb0);
    cudaGetSymbolAddress((void**)&emb1, g_emb1);
    cudaGetSymbolAddress((void**)&pR,   g_pR);
    cudaGetSymbolAddress((void**)&yl,   g_yleaf);

    // Encoder: 4 relu dense layers (ping-pong)
    gemm_relu_kernel<<<128, 256>>>(x,    enc_W,             enc_b,       emb0);
    gemm_relu_kernel<<<128, 256>>>(emb0, enc_W + 1 * 65536, enc_b + 256, emb1);
    gemm_relu_kernel<<<128, 256>>>(emb1, enc_W + 2 * 65536, enc_b + 512, emb0);
    gemm_relu_kernel<<<128, 256>>>(emb0, enc_W + 3 * 65536, enc_b + 768, emb1);

    // Inner gates
    const int inner_smem = INNER_SMEM_FLOATS * (int)sizeof(float);
    cudaFuncSetAttribute(inner_kernel,
                         cudaFuncAttributeMaxDynamicSharedMemorySize, inner_smem);
    inner_kernel<<<dim3(BATCH / 64, N_INNER), 256, inner_smem>>>(
        emb1, x, in_W1, in_b1, in_Ww, in_bw, in_Wb, in_bb, in_Wbt, in_bbt, pR);

    // Leaf MLPs
    leaf_kernel<<<dim3(BATCH / 64, N_LEAF), 256>>>(emb1, lf_W1, lf_b1, lf_W2, lf_b2, yl);

    // Combine
    combine_kernel<<<BATCH / 256, 256>>>(pR, yl, out);
}

// round 3
// speedup vs baseline: 1.8280x; 1.8280x over previous
#include <cuda_runtime.h>
#include <cuda_bf16.h>
#include <cstdint>
#include <math.h>

#define BATCH 8192
#define EDIM  256
#define HDIM  50
#define N_INNER 31
#define N_LEAF  32

// ---------------------------------------------------------------------------
// Device scratch
// ---------------------------------------------------------------------------
__device__ float g_emb[BATCH * EDIM];
__device__ float g_pR[N_INNER * BATCH];
__device__ float g_yleaf[N_LEAF * BATCH];

__device__ __nv_bfloat16 g_xh[BATCH * EDIM];
__device__ __nv_bfloat16 g_xl[BATCH * EDIM];
__device__ __nv_bfloat16 g_e0h[BATCH * EDIM];
__device__ __nv_bfloat16 g_e0l[BATCH * EDIM];
__device__ __nv_bfloat16 g_e1h[BATCH * EDIM];
__device__ __nv_bfloat16 g_e1l[BATCH * EDIM];
// transposed weights: 0..3 encoder, 4..35 leaves. layout [mat][N=256][K=256]
__device__ __nv_bfloat16 g_wth[36 * 65536];
__device__ __nv_bfloat16 g_wtl[36 * 65536];

// ---------------------------------------------------------------------------
// Helpers
// ---------------------------------------------------------------------------
__device__ __forceinline__ uint32_t smem_u32(const void* p) {
    uint32_t a;
    asm("{ .reg .u64 t; cvta.to.shared.u64 t, %1; cvt.u32.u64 %0, t; }" : "=r"(a) : "l"(p));
    return a;
}
#define CP_ASYNC16(dst, src) \
    asm volatile("cp.async.cg.shared.global [%0], [%1], 16;" :: "r"(dst), "l"(src) : "memory")
#define CP_COMMIT() asm volatile("cp.async.commit_group;" ::: "memory")
#define CP_WAIT1()  asm volatile("cp.async.wait_group 1;" ::: "memory")
#define CP_WAIT0()  asm volatile("cp.async.wait_group 0;" ::: "memory")

#define LDSM4(r, addr) \
    asm volatile("ldmatrix.sync.aligned.m8n8.x4.shared.b16 {%0,%1,%2,%3}, [%4];" \
        : "=r"((r)[0]), "=r"((r)[1]), "=r"((r)[2]), "=r"((r)[3]) : "r"(addr))

__device__ __forceinline__ void mma_bf16(float* c, const uint32_t* a, const uint32_t* b) {
    asm volatile(
        "mma.sync.aligned.m16n8k16.row.col.f32.bf16.bf16.f32 "
        "{%0,%1,%2,%3}, {%4,%5,%6,%7}, {%8,%9}, {%0,%1,%2,%3};"
        : "+f"(c[0]), "+f"(c[1]), "+f"(c[2]), "+f"(c[3])
        : "r"(a[0]), "r"(a[1]), "r"(a[2]), "r"(a[3]), "r"(b[0]), "r"(b[1]));
}

// ---------------------------------------------------------------------------
// Prep: x f32 -> bf16 hi/lo
// ---------------------------------------------------------------------------
__global__ __launch_bounds__(256) void prep_x_kernel(
    const float* __restrict__ x, __nv_bfloat16* __restrict__ xh,
    __nv_bfloat16* __restrict__ xl)
{
    int i = blockIdx.x * 256 + threadIdx.x;    // float4 index
    float4 v = ((const float4*)x)[i];
    float f[4] = {v.x, v.y, v.z, v.w};
    __nv_bfloat16 h[4], l[4];
#pragma unroll
    for (int j = 0; j < 4; j++) {
        h[j] = __float2bfloat16(f[j]);
        l[j] = __float2bfloat16(f[j] - __bfloat162float(h[j]));
    }
    *(uint2*)(xh + 4 * (size_t)i) = *(uint2*)h;
    *(uint2*)(xl + 4 * (size_t)i) = *(uint2*)l;
}

// ---------------------------------------------------------------------------
// Prep: transpose [K][N] f32 -> [N][K] bf16 hi/lo per 256x256 matrix
// ---------------------------------------------------------------------------
__global__ __launch_bounds__(256) void prep_w_kernel(
    const float* __restrict__ W, __nv_bfloat16* __restrict__ th,
    __nv_bfloat16* __restrict__ tl)
{
    __shared__ float t[32][33];
    const int mat = blockIdx.z;
    const int nb = blockIdx.x * 32, kb = blockIdx.y * 32;
    const int tx = threadIdx.x, ty = threadIdx.y;
    const float* src = W + (size_t)mat * 65536;
#pragma unroll
    for (int i = 0; i < 4; i++)
        t[ty + 8 * i][tx] = src[(size_t)(kb + ty + 8 * i) * 256 + nb + tx];
    __syncthreads();
#pragma unroll
    for (int i = 0; i < 4; i++) {
        float v = t[tx][ty + 8 * i];
        size_t idx = (size_t)mat * 65536 + (size_t)(nb + ty + 8 * i) * 256 + kb + tx;
        __nv_bfloat16 h = __float2bfloat16(v);
        th[idx] = h;
        tl[idx] = __float2bfloat16(v - __bfloat162float(h));
    }
}

// ---------------------------------------------------------------------------
// Zero yleaf (leaf kernel accumulates with atomicAdd)
// ---------------------------------------------------------------------------
__global__ __launch_bounds__(256) void zero_kernel(float* __restrict__ p) {
    int i = blockIdx.x * 256 + threadIdx.x;
    ((float4*)p)[i] = make_float4(0.f, 0.f, 0.f, 0.f);
}

// ---------------------------------------------------------------------------
// mma.sync GEMM: C[128,128] tile of A[8192,256] @ B[mat]^T (B stored [N][K])
// bf16 hi/lo 3-MMA emulation, fp32 accumulate.
// MODE 0 (encoder): relu(C+bias) -> optional f32 + bf16 hi/lo
// MODE 1 (leaf):    atomicAdd(yleaf, sum_n relu(C+b1)*W2)
// ---------------------------------------------------------------------------
#define SA_BYTES   80                    // padded row stride: 40 bf16
#define TILE_BYTES 10240                 // 128 rows * 80B
#define STAGE_BYTES (4 * TILE_BYTES)     // Ah, Al, Bh, Bl
#define MM_SMEM (2 * STAGE_BYTES + 1024) // + bias/w2 for leaf

template <int MODE>
__global__ __launch_bounds__(256) void mm_kernel(
    const __nv_bfloat16* __restrict__ Ah, const __nv_bfloat16* __restrict__ Al,
    const __nv_bfloat16* __restrict__ Bh, const __nv_bfloat16* __restrict__ Bl,
    const float* __restrict__ bias, const float* __restrict__ w2,
    float* __restrict__ outf, __nv_bfloat16* __restrict__ oh,
    __nv_bfloat16* __restrict__ ol, float* __restrict__ yleaf)
{
    extern __shared__ char smem[];
    const uint32_t sbase = smem_u32(smem);
    const int tid = threadIdx.x;
    const int lane = tid & 31, warp = tid >> 5;
    const int m0 = blockIdx.x * 128;
    const int n0 = blockIdx.y * 128;
    const int mat = (MODE == 1) ? blockIdx.z : 0;
    const int wm = (warp >> 1) * 32;   // warp m-offset within tile
    const int wn = (warp & 1) * 64;    // warp n-offset within tile

    const __nv_bfloat16* bhp = Bh + (size_t)mat * 65536;
    const __nv_bfloat16* blp = Bl + (size_t)mat * 65536;

    float* s_bias = (float*)(smem + 2 * STAGE_BYTES);
    float* s_w2   = (float*)(smem + 2 * STAGE_BYTES + 512);
    if (MODE == 1 && tid < 128) {
        s_bias[tid] = bias[(size_t)mat * 256 + n0 + tid];
        s_w2[tid]   = w2[(size_t)mat * 256 + n0 + tid];
    }

    float c[2][8][4];
#pragma unroll
    for (int mf = 0; mf < 2; mf++)
#pragma unroll
        for (int nf = 0; nf < 8; nf++)
#pragma unroll
            for (int q = 0; q < 4; q++) c[mf][nf][q] = 0.f;

    // cp.async assignment: thread covers rows (tid>>2) and (tid>>2)+64, unit tid&3
    const int crow = tid >> 2;
    const int cu   = tid & 3;

    // ldmatrix per-lane offsets
    const int arow = (lane & 7) + ((lane >> 3) & 1) * 8;
    const int acol = (lane >> 4) * 8;
    const int brow = (lane & 7) + (lane >> 4) * 8;
    const int bcol = ((lane >> 3) & 1) * 8;

#define ISSUE_CHUNK(CI) do {                                                    \
    const int k0_ = (CI) * 32;                                                  \
    const uint32_t st_ = sbase + ((CI) & 1) * STAGE_BYTES;                      \
    const uint32_t d0 = st_ + crow * SA_BYTES + cu * 16;                        \
    const uint32_t d1 = st_ + (crow + 64) * SA_BYTES + cu * 16;                 \
    const size_t ga = (size_t)(m0 + crow) * 256 + k0_ + cu * 8;                 \
    const size_t gb = (size_t)(n0 + crow) * 256 + k0_ + cu * 8;                 \
    CP_ASYNC16(d0,                      Ah + ga);                               \
    CP_ASYNC16(d1,                      Ah + ga + 64 * 256);                    \
    CP_ASYNC16(d0 + TILE_BYTES,         Al + ga);                               \
    CP_ASYNC16(d1 + TILE_BYTES,         Al + ga + 64 * 256);                    \
    CP_ASYNC16(d0 + 2 * TILE_BYTES,     bhp + gb);                              \
    CP_ASYNC16(d1 + 2 * TILE_BYTES,     bhp + gb + 64 * 256);                   \
    CP_ASYNC16(d0 + 3 * TILE_BYTES,     blp + gb);                              \
    CP_ASYNC16(d1 + 3 * TILE_BYTES,     blp + gb + 64 * 256);                   \
    CP_COMMIT();                                                                \
} while (0)

    ISSUE_CHUNK(0);

#pragma unroll 1
    for (int ci = 0; ci < 8; ci++) {
        if (ci < 7) { ISSUE_CHUNK(ci + 1); CP_WAIT1(); }
        else        { CP_WAIT0(); }
        __syncthreads();

        const uint32_t st = sbase + (ci & 1) * STAGE_BYTES;
#pragma unroll
        for (int kk = 0; kk < 32; kk += 16) {
            uint32_t ah[2][4], al[2][4];
#pragma unroll
            for (int mf = 0; mf < 2; mf++) {
                uint32_t addr = st + (wm + mf * 16 + arow) * SA_BYTES + (kk + acol) * 2;
                LDSM4(ah[mf], addr);
                LDSM4(al[mf], addr + TILE_BYTES);
            }
            uint32_t bhf[8][2], blf[8][2];
#pragma unroll
            for (int np = 0; np < 4; np++) {
                uint32_t addr = st + 2 * TILE_BYTES
                              + (wn + np * 16 + brow) * SA_BYTES + (kk + bcol) * 2;
                uint32_t r[4];
                LDSM4(r, addr);
                bhf[2 * np][0] = r[0]; bhf[2 * np][1] = r[1];
                bhf[2 * np + 1][0] = r[2]; bhf[2 * np + 1][1] = r[3];
                LDSM4(r, addr + TILE_BYTES);
                blf[2 * np][0] = r[0]; blf[2 * np][1] = r[1];
                blf[2 * np + 1][0] = r[2]; blf[2 * np + 1][1] = r[3];
            }
#pragma unroll
            for (int mf = 0; mf < 2; mf++)
#pragma unroll
                for (int nf = 0; nf < 8; nf++) {
                    mma_bf16(c[mf][nf], ah[mf], bhf[nf]);
                    mma_bf16(c[mf][nf], ah[mf], blf[nf]);
                    mma_bf16(c[mf][nf], al[mf], bhf[nf]);
                }
        }
        __syncthreads();
    }

    // ---------------- Epilogue ----------------
    const int erow = lane >> 2;
    const int ecol = (lane & 3) * 2;

    if (MODE == 0) {
#pragma unroll
        for (int mf = 0; mf < 2; mf++) {
            const int gr0 = m0 + wm + mf * 16 + erow;
#pragma unroll
            for (int nf = 0; nf < 8; nf++) {
                const int gc = n0 + wn + nf * 8 + ecol;
                float2 bb = *(const float2*)&bias[gc];
                float v00 = fmaxf(c[mf][nf][0] + bb.x, 0.f);
                float v01 = fmaxf(c[mf][nf][1] + bb.y, 0.f);
                float v10 = fmaxf(c[mf][nf][2] + bb.x, 0.f);
                float v11 = fmaxf(c[mf][nf][3] + bb.y, 0.f);
                const size_t i0 = (size_t)gr0 * 256 + gc;
                const size_t i1 = (size_t)(gr0 + 8) * 256 + gc;
                if (outf) {
                    *(float2*)(outf + i0) = make_float2(v00, v01);
                    *(float2*)(outf + i1) = make_float2(v10, v11);
                }
                __nv_bfloat16 h00 = __float2bfloat16(v00), h01 = __float2bfloat16(v01);
                __nv_bfloat16 h10 = __float2bfloat16(v10), h11 = __float2bfloat16(v11);
                __nv_bfloat16 p0[2] = {h00, h01}, p1[2] = {h10, h11};
                *(uint32_t*)(oh + i0) = *(uint32_t*)p0;
                *(uint32_t*)(oh + i1) = *(uint32_t*)p1;
                __nv_bfloat16 q0[2] = {__float2bfloat16(v00 - __bfloat162float(h00)),
                                       __float2bfloat16(v01 - __bfloat162float(h01))};
                __nv_bfloat16 q1[2] = {__float2bfloat16(v10 - __bfloat162float(h10)),
                                       __float2bfloat16(v11 - __bfloat162float(h11))};
                *(uint32_t*)(ol + i0) = *(uint32_t*)q0;
                *(uint32_t*)(ol + i1) = *(uint32_t*)q1;
            }
        }
    } else {
        float part[2][2] = {{0.f, 0.f}, {0.f, 0.f}};
#pragma unroll
        for (int mf = 0; mf < 2; mf++)
#pragma unroll
            for (int nf = 0; nf < 8; nf++) {
                const int lc = wn + nf * 8 + ecol;
                const float b0s = s_bias[lc], b1s = s_bias[lc + 1];
                const float w0 = s_w2[lc], w1 = s_w2[lc + 1];
                part[mf][0] = fmaf(fmaxf(c[mf][nf][0] + b0s, 0.f), w0, part[mf][0]);
                part[mf][0] = fmaf(fmaxf(c[mf][nf][1] + b1s, 0.f), w1, part[mf][0]);
                part[mf][1] = fmaf(fmaxf(c[mf][nf][2] + b0s, 0.f), w0, part[mf][1]);
                part[mf][1] = fmaf(fmaxf(c[mf][nf][3] + b1s, 0.f), w1, part[mf][1]);
            }
#pragma unroll
        for (int mf = 0; mf < 2; mf++)
#pragma unroll
            for (int h = 0; h < 2; h++) {
                part[mf][h] += __shfl_xor_sync(0xffffffffu, part[mf][h], 1);
                part[mf][h] += __shfl_xor_sync(0xffffffffu, part[mf][h], 2);
            }
        if ((lane & 3) == 0) {
#pragma unroll
            for (int mf = 0; mf < 2; mf++)
#pragma unroll
                for (int h = 0; h < 2; h++) {
                    const int row = m0 + wm + mf * 16 + h * 8 + erow;
                    atomicAdd(&yleaf[(size_t)mat * BATCH + row], part[mf][h]);
                }
        }
    }
#undef ISSUE_CHUNK
}

// ---------------------------------------------------------------------------
// Inner-node kernel (fp32 SIMT, unchanged from round 1)
// ---------------------------------------------------------------------------
#define INNER_SMEM_FLOATS (16*68 + 16*64 + 64*65 + 50*256)

__global__ __launch_bounds__(256) void inner_kernel(
    const float* __restrict__ emb, const float* __restrict__ x,
    const float* __restrict__ W1, const float* __restrict__ b1,
    const float* __restrict__ Ww, const float* __restrict__ bw,
    const float* __restrict__ Wb, const float* __restrict__ bbias,
    const float* __restrict__ Wbeta, const float* __restrict__ bbeta,
    float* __restrict__ pR)
{
    extern __shared__ float sm[];
    float* As  = sm;                        // [16][68]
    float* W1s = sm + 16 * 68;              // [16][64]
    float* Hs  = sm + 16 * 68 + 16 * 64;    // [64][65]
    float* Wws = Hs + 64 * 65;              // [50][256]

    const int n  = blockIdx.y;
    const int m0 = blockIdx.x * 64;
    const int t  = threadIdx.x;

    {
        const float* src = Ww + (size_t)n * HDIM * 256;
        for (int i = t; i < (HDIM * 256) / 4; i += 256)
            *(float4*)&Wws[i * 4] = *(const float4*)&src[i * 4];
    }

    const int rg = t & 15;
    const int cg = t >> 4;
    float acc[4][4];
#pragma unroll
    for (int i = 0; i < 4; i++)
#pragma unroll
        for (int q = 0; q < 4; q++) acc[i][q] = 0.f;

    const int lm  = t >> 2;
    const int lkv = (t & 3) * 4;
    const int w1k = t >> 4;
    const int w1j = (t & 15) * 4;

    for (int k0 = 0; k0 < 256; k0 += 16) {
        float4 a0 = *(const float4*)&emb[(size_t)(m0 + lm) * 256 + k0 + lkv];
        As[(lkv + 0) * 68 + lm] = a0.x; As[(lkv + 1) * 68 + lm] = a0.y;
        As[(lkv + 2) * 68 + lm] = a0.z; As[(lkv + 3) * 68 + lm] = a0.w;
#pragma unroll
        for (int u = 0; u < 4; u++) {
            int j = w1j + u;
            W1s[w1k * 64 + j] = (j < HDIM)
                ? W1[((size_t)n * 256 + k0 + w1k) * HDIM + j] : 0.f;
        }
        __syncthreads();
#pragma unroll
        for (int k = 0; k < 16; k++) {
            float a[4], w[4];
#pragma unroll
            for (int i = 0; i < 4; i++) a[i] = As[k * 68 + rg * 4 + i];
#pragma unroll
            for (int q = 0; q < 4; q++) w[q] = W1s[k * 64 + cg * 4 + q];
#pragma unroll
            for (int i = 0; i < 4; i++)
#pragma unroll
                for (int q = 0; q < 4; q++) acc[i][q] = fmaf(a[i], w[q], acc[i][q]);
        }
        __syncthreads();
    }
#pragma unroll
    for (int i = 0; i < 4; i++)
#pragma unroll
        for (int q = 0; q < 4; q++) {
            int cix = cg * 4 + q;
            float v = acc[i][q] + ((cix < HDIM) ? b1[n * HDIM + cix] : 0.f);
            Hs[(rg * 4 + i) * 65 + cix] = fmaxf(v, 0.f);
        }
    __syncthreads();

    const int lane = t & 31;
    const int wrp  = t >> 5;

    float bwv[8];
#pragma unroll
    for (int u = 0; u < 8; u++) bwv[u] = bw[n * 256 + lane + 32 * u];

    const float wbb   = bbias[n];
    const float wbetb = bbeta[n];

#pragma unroll
    for (int g = 0; g < 2; g++) {
        const int r0 = wrp * 8 + g * 4;
        float z[4][8];
#pragma unroll
        for (int rr = 0; rr < 4; rr++)
#pragma unroll
            for (int u = 0; u < 8; u++) z[rr][u] = bwv[u];

        for (int j = 0; j < HDIM; j++) {
            float h0 = Hs[(r0 + 0) * 65 + j];
            float h1 = Hs[(r0 + 1) * 65 + j];
            float h2 = Hs[(r0 + 2) * 65 + j];
            float h3 = Hs[(r0 + 3) * 65 + j];
#pragma unroll
            for (int u = 0; u < 8; u++) {
                float wv = Wws[j * 256 + lane + 32 * u];
                z[0][u] = fmaf(h0, wv, z[0][u]);
                z[1][u] = fmaf(h1, wv, z[1][u]);
                z[2][u] = fmaf(h2, wv, z[2][u]);
                z[3][u] = fmaf(h3, wv, z[3][u]);
            }
        }

#pragma unroll
        for (int rr = 0; rr < 4; rr++) {
            const int r = r0 + rr;
            float mx = z[rr][0];
#pragma unroll
            for (int u = 1; u < 8; u++) mx = fmaxf(mx, z[rr][u]);
#pragma unroll
            for (int off = 16; off; off >>= 1)
                mx = fmaxf(mx, __shfl_xor_sync(0xffffffffu, mx, off));

            float se = 0.f, sx = 0.f;
            const float* xr = x + (size_t)(m0 + r) * 256;
#pragma unroll
            for (int u = 0; u < 8; u++) {
                float e = expf(z[rr][u] - mx);
                se += e;
                sx = fmaf(e, xr[lane + 32 * u], sx);
            }
            float pb = 0.f, pbt = 0.f;
            for (int j = lane; j < HDIM; j += 32) {
                float hv = Hs[r * 65 + j];
                pb  = fmaf(hv, Wb[n * HDIM + j], pb);
                pbt = fmaf(hv, Wbeta[n * HDIM + j], pbt);
            }
#pragma unroll
            for (int off = 16; off; off >>= 1) {
                se  += __shfl_xor_sync(0xffffffffu, se, off);
                sx  += __shfl_xor_sync(0xffffffffu, sx, off);
                pb  += __shfl_xor_sync(0xffffffffu, pb, off);
                pbt += __shfl_xor_sync(0xffffffffu, pbt, off);
            }
            if (lane == 0) {
                float bv   = pb + wbb;
                float beta = pbt + wbetb;
                float val  = beta * (sx / se + bv);
                pR[(size_t)n * BATCH + m0 + r] = 1.0f / (1.0f + expf(-val));
            }
        }
    }
}

// ---------------------------------------------------------------------------
// Combine: out[b] = sum_leaf prob(leaf,b) * (y_leaf[leaf,b] + b2[leaf])
// ---------------------------------------------------------------------------
__global__ __launch_bounds__(256) void combine_kernel(
    const float* __restrict__ pR, const float* __restrict__ yl,
    const float* __restrict__ b2, float* __restrict__ out)
{
    const int b = blockIdx.x * 256 + threadIdx.x;
    float p[N_INNER];
#pragma unroll
    for (int i = 0; i < N_INNER; i++) p[i] = pR[(size_t)i * BATCH + b];

    float prob[N_LEAF];
    prob[0] = 1.f;
#pragma unroll
    for (int lev = 0; lev < 5; lev++) {
        const int cnt = 1 << lev;
        const int off = cnt - 1;
#pragma unroll
        for (int i = N_LEAF - 1; i >= 0; i--) {
            if (i < cnt) {
                float pr   = p[off + i];
                float base = prob[i];
                prob[2 * i]     = base * (1.f - pr);
                prob[2 * i + 1] = base * pr;
            }
        }
    }
    float acc = 0.f;
#pragma unroll
    for (int l = 0; l < N_LEAF; l++)
        acc = fmaf(prob[l], yl[(size_t)l * BATCH + b] + b2[l], acc);
    out[b] = acc;
}

// ---------------------------------------------------------------------------
extern "C" void kernel_launch(void* const* d_in, const int* in_sizes, int n_in,
                              void* d_out, int out_size)
{
    const float* x       = (const float*)d_in[0];
    const float* enc_W   = (const float*)d_in[1];
    const float* enc_b   = (const float*)d_in[2];
    const float* in_W1   = (const float*)d_in[3];
    const float* in_b1   = (const float*)d_in[4];
    const float* in_Ww   = (const float*)d_in[5];
    const float* in_bw   = (const float*)d_in[6];
    const float* in_Wb   = (const float*)d_in[7];
    const float* in_bb   = (const float*)d_in[8];
    const float* in_Wbt  = (const float*)d_in[9];
    const float* in_bbt  = (const float*)d_in[10];
    const float* lf_W1   = (const float*)d_in[11];
    const float* lf_b1   = (const float*)d_in[12];
    const float* lf_W2   = (const float*)d_in[13];
    const float* lf_b2   = (const float*)d_in[14];
    float* out = (float*)d_out;

    float *emb, *pR, *yl;
    __nv_bfloat16 *xh, *xl, *e0h, *e0l, *e1h, *e1l, *wth, *wtl;
    cudaGetSymbolAddress((void**)&emb, g_emb);
    cudaGetSymbolAddress((void**)&pR,  g_pR);
    cudaGetSymbolAddress((void**)&yl,  g_yleaf);
    cudaGetSymbolAddress((void**)&xh,  g_xh);
    cudaGetSymbolAddress((void**)&xl,  g_xl);
    cudaGetSymbolAddress((void**)&e0h, g_e0h);
    cudaGetSymbolAddress((void**)&e0l, g_e0l);
    cudaGetSymbolAddress((void**)&e1h, g_e1h);
    cudaGetSymbolAddress((void**)&e1l, g_e1l);
    cudaGetSymbolAddress((void**)&wth, g_wth);
    cudaGetSymbolAddress((void**)&wtl, g_wtl);

    cudaFuncSetAttribute(mm_kernel<0>, cudaFuncAttributeMaxDynamicSharedMemorySize, MM_SMEM);
    cudaFuncSetAttribute(mm_kernel<1>, cudaFuncAttributeMaxDynamicSharedMemorySize, MM_SMEM);

    // --- prep ---
    prep_x_kernel<<<BATCH * EDIM / 1024, 256>>>(x, xh, xl);
    prep_w_kernel<<<dim3(8, 8, 4),  dim3(32, 8)>>>(enc_W, wth, wtl);
    prep_w_kernel<<<dim3(8, 8, 32), dim3(32, 8)>>>(lf_W1, wth + 4 * 65536, wtl + 4 * 65536);
    zero_kernel<<<N_LEAF * BATCH / 1024, 256>>>(yl);

    // --- encoder: 4 layers (grid 64 x 2 n-tiles) ---
    mm_kernel<0><<<dim3(64, 2), 256, MM_SMEM>>>(xh, xl, wth, wtl,
        enc_b, nullptr, nullptr, e0h, e0l, nullptr);
    mm_kernel<0><<<dim3(64, 2), 256, MM_SMEM>>>(e0h, e0l, wth + 65536, wtl + 65536,
        enc_b + 256, nullptr, nullptr, e1h, e1l, nullptr);
    mm_kernel<0><<<dim3(64, 2), 256, MM_SMEM>>>(e1h, e1l, wth + 2 * 65536, wtl + 2 * 65536,
        enc_b + 512, nullptr, nullptr, e0h, e0l, nullptr);
    mm_kernel<0><<<dim3(64, 2), 256, MM_SMEM>>>(e0h, e0l, wth + 3 * 65536, wtl + 3 * 65536,
        enc_b + 768, nullptr, emb, e1h, e1l, nullptr);

    // --- inner gates (fp32 SIMT) ---
    const int inner_smem = INNER_SMEM_FLOATS * (int)sizeof(float);
    cudaFuncSetAttribute(inner_kernel, cudaFuncAttributeMaxDynamicSharedMemorySize, inner_smem);
    inner_kernel<<<dim3(BATCH / 64, N_INNER), 256, inner_smem>>>(
        emb, x, in_W1, in_b1, in_Ww, in_bw, in_Wb, in_bb, in_Wbt, in_bbt, pR);

    // --- leaves (mma.sync, atomicAdd into yl) ---
    mm_kernel<1><<<dim3(64, 2, N_LEAF), 256, MM_SMEM>>>(
        e1h, e1l, wth + 4 * 65536, wtl + 4 * 65536,
        lf_b1, lf_W2, nullptr, nullptr, nullptr, yl);

    // --- combine (adds b2) ---
    combine_kernel<<<BATCH / 256, 256>>>(pR, yl, lf_b2, out);
}

// round 4
// speedup vs baseline: 2.4661x; 1.3490x over previous
#include <cuda_runtime.h>
#include <cuda_bf16.h>
#include <cstdint>
#include <math.h>

#define BATCH 8192
#define EDIM  256
#define HDIM  50
#define N_INNER 31
#define N_LEAF  32

// ---------------------------------------------------------------------------
// Device scratch
// ---------------------------------------------------------------------------
__device__ float g_pR[N_INNER * BATCH];
__device__ float g_yleaf[N_LEAF * BATCH];

__device__ __nv_bfloat16 g_xh[BATCH * EDIM];
__device__ __nv_bfloat16 g_xl[BATCH * EDIM];
__device__ __nv_bfloat16 g_e0h[BATCH * EDIM];
__device__ __nv_bfloat16 g_e0l[BATCH * EDIM];
__device__ __nv_bfloat16 g_e1h[BATCH * EDIM];
__device__ __nv_bfloat16 g_e1l[BATCH * EDIM];
// transposed weights: 0..3 encoder, 4..35 leaves. layout [mat][N=256][K=256]
__device__ __nv_bfloat16 g_wth[36 * 65536];
__device__ __nv_bfloat16 g_wtl[36 * 65536];
// inner: W1 transposed [31][64][256] (rows 50..63 zero)
__device__ __nv_bfloat16 g_w1th[N_INNER * 64 * 256];
__device__ __nv_bfloat16 g_w1tl[N_INNER * 64 * 256];
// inner: Ww transposed [31][256][64] (cols 50..63 zero)
__device__ __nv_bfloat16 g_wwth[N_INNER * 256 * 64];
__device__ __nv_bfloat16 g_wwtl[N_INNER * 256 * 64];

// ---------------------------------------------------------------------------
// Helpers
// ---------------------------------------------------------------------------
__device__ __forceinline__ uint32_t smem_u32(const void* p) {
    uint32_t a;
    asm("{ .reg .u64 t; cvta.to.shared.u64 t, %1; cvt.u32.u64 %0, t; }" : "=r"(a) : "l"(p));
    return a;
}
#define CP_ASYNC16(dst, src) \
    asm volatile("cp.async.cg.shared.global [%0], [%1], 16;" :: "r"(dst), "l"(src) : "memory")
#define CP_COMMIT() asm volatile("cp.async.commit_group;" ::: "memory")
#define CP_WAIT2()  asm volatile("cp.async.wait_group 2;" ::: "memory")
#define CP_WAIT1()  asm volatile("cp.async.wait_group 1;" ::: "memory")
#define CP_WAIT0()  asm volatile("cp.async.wait_group 0;" ::: "memory")

#define LDSM4(r, addr) \
    asm volatile("ldmatrix.sync.aligned.m8n8.x4.shared.b16 {%0,%1,%2,%3}, [%4];" \
        : "=r"((r)[0]), "=r"((r)[1]), "=r"((r)[2]), "=r"((r)[3]) : "r"(addr))

__device__ __forceinline__ void mma_bf16(float* c, const uint32_t* a, const uint32_t* b) {
    asm volatile(
        "mma.sync.aligned.m16n8k16.row.col.f32.bf16.bf16.f32 "
        "{%0,%1,%2,%3}, {%4,%5,%6,%7}, {%8,%9}, {%0,%1,%2,%3};"
        : "+f"(c[0]), "+f"(c[1]), "+f"(c[2]), "+f"(c[3])
        : "r"(a[0]), "r"(a[1]), "r"(a[2]), "r"(a[3]), "r"(b[0]), "r"(b[1]));
}

__device__ __forceinline__ void split2(float a, float b, uint32_t& hi, uint32_t& lo) {
    __nv_bfloat16 h0 = __float2bfloat16(a), h1 = __float2bfloat16(b);
    __nv_bfloat16 l0 = __float2bfloat16(a - __bfloat162float(h0));
    __nv_bfloat16 l1 = __float2bfloat16(b - __bfloat162float(h1));
    __nv_bfloat16 hh[2] = {h0, h1}, ll[2] = {l0, l1};
    hi = *(uint32_t*)hh;
    lo = *(uint32_t*)ll;
}

// ---------------------------------------------------------------------------
// Prep kernels
// ---------------------------------------------------------------------------
__global__ __launch_bounds__(256) void prep_x_kernel(
    const float* __restrict__ x, __nv_bfloat16* __restrict__ xh,
    __nv_bfloat16* __restrict__ xl)
{
    int i = blockIdx.x * 256 + threadIdx.x;
    float4 v = ((const float4*)x)[i];
    float f[4] = {v.x, v.y, v.z, v.w};
    __nv_bfloat16 h[4], l[4];
#pragma unroll
    for (int j = 0; j < 4; j++) {
        h[j] = __float2bfloat16(f[j]);
        l[j] = __float2bfloat16(f[j] - __bfloat162float(h[j]));
    }
    *(uint2*)(xh + 4 * (size_t)i) = *(uint2*)h;
    *(uint2*)(xl + 4 * (size_t)i) = *(uint2*)l;
}

__global__ __launch_bounds__(256) void prep_w_kernel(
    const float* __restrict__ W, __nv_bfloat16* __restrict__ th,
    __nv_bfloat16* __restrict__ tl)
{
    __shared__ float t[32][33];
    const int mat = blockIdx.z;
    const int nb = blockIdx.x * 32, kb = blockIdx.y * 32;
    const int tx = threadIdx.x, ty = threadIdx.y;
    const float* src = W + (size_t)mat * 65536;
#pragma unroll
    for (int i = 0; i < 4; i++)
        t[ty + 8 * i][tx] = src[(size_t)(kb + ty + 8 * i) * 256 + nb + tx];
    __syncthreads();
#pragma unroll
    for (int i = 0; i < 4; i++) {
        float v = t[tx][ty + 8 * i];
        size_t idx = (size_t)mat * 65536 + (size_t)(nb + ty + 8 * i) * 256 + kb + tx;
        __nv_bfloat16 h = __float2bfloat16(v);
        th[idx] = h;
        tl[idx] = __float2bfloat16(v - __bfloat162float(h));
    }
}

// W1 [31][256][50] -> [31][64][256] bf16 hi/lo  (out n-major, pad to 64)
__global__ __launch_bounds__(256) void prep_w1_kernel(
    const float* __restrict__ W1, __nv_bfloat16* __restrict__ th,
    __nv_bfloat16* __restrict__ tl)
{
    int idx = blockIdx.x * 256 + threadIdx.x;      // over 31*64*256
    int k = idx & 255, j = (idx >> 8) & 63, n = idx >> 14;
    float v = (j < HDIM) ? W1[((size_t)n * 256 + k) * HDIM + j] : 0.f;
    __nv_bfloat16 h = __float2bfloat16(v);
    th[idx] = h;
    tl[idx] = __float2bfloat16(v - __bfloat162float(h));
}

// Ww [31][50][256] -> [31][256][64] bf16 hi/lo (pad k to 64)
__global__ __launch_bounds__(256) void prep_ww_kernel(
    const float* __restrict__ Ww, __nv_bfloat16* __restrict__ th,
    __nv_bfloat16* __restrict__ tl)
{
    int idx = blockIdx.x * 256 + threadIdx.x;      // over 31*256*64
    int j = idx & 63, d = (idx >> 6) & 255, n = idx >> 14;
    float v = (j < HDIM) ? Ww[((size_t)n * HDIM + j) * 256 + d] : 0.f;
    __nv_bfloat16 h = __float2bfloat16(v);
    th[idx] = h;
    tl[idx] = __float2bfloat16(v - __bfloat162float(h));
}

__global__ __launch_bounds__(256) void zero_kernel(float* __restrict__ p) {
    int i = blockIdx.x * 256 + threadIdx.x;
    ((float4*)p)[i] = make_float4(0.f, 0.f, 0.f, 0.f);
}

// ---------------------------------------------------------------------------
// mma.sync GEMM (same as round 3): C[128,128] tile, bf16 hi/lo 3-MMA.
// MODE 0 (encoder): relu(C+bias) -> bf16 hi/lo
// MODE 1 (leaf):    atomicAdd(yleaf, sum_n relu(C+b1)*W2)
// ---------------------------------------------------------------------------
#define SA_BYTES   80
#define TILE_BYTES 10240
#define STAGE_BYTES (4 * TILE_BYTES)
#define MM_SMEM (2 * STAGE_BYTES + 1024)

template <int MODE>
__global__ __launch_bounds__(256) void mm_kernel(
    const __nv_bfloat16* __restrict__ Ah, const __nv_bfloat16* __restrict__ Al,
    const __nv_bfloat16* __restrict__ Bh, const __nv_bfloat16* __restrict__ Bl,
    const float* __restrict__ bias, const float* __restrict__ w2,
    __nv_bfloat16* __restrict__ oh, __nv_bfloat16* __restrict__ ol,
    float* __restrict__ yleaf)
{
    extern __shared__ char smem[];
    const uint32_t sbase = smem_u32(smem);
    const int tid = threadIdx.x;
    const int lane = tid & 31, warp = tid >> 5;
    const int m0 = blockIdx.x * 128;
    const int n0 = blockIdx.y * 128;
    const int mat = (MODE == 1) ? blockIdx.z : 0;
    const int wm = (warp >> 1) * 32;
    const int wn = (warp & 1) * 64;

    const __nv_bfloat16* bhp = Bh + (size_t)mat * 65536;
    const __nv_bfloat16* blp = Bl + (size_t)mat * 65536;

    float* s_bias = (float*)(smem + 2 * STAGE_BYTES);
    float* s_w2   = (float*)(smem + 2 * STAGE_BYTES + 512);
    if (MODE == 1 && tid < 128) {
        s_bias[tid] = bias[(size_t)mat * 256 + n0 + tid];
        s_w2[tid]   = w2[(size_t)mat * 256 + n0 + tid];
    }

    float c[2][8][4];
#pragma unroll
    for (int mf = 0; mf < 2; mf++)
#pragma unroll
        for (int nf = 0; nf < 8; nf++)
#pragma unroll
            for (int q = 0; q < 4; q++) c[mf][nf][q] = 0.f;

    const int crow = tid >> 2;
    const int cu   = tid & 3;
    const int arow = (lane & 7) + ((lane >> 3) & 1) * 8;
    const int acol = (lane >> 4) * 8;
    const int brow = (lane & 7) + (lane >> 4) * 8;
    const int bcol = ((lane >> 3) & 1) * 8;

#define ISSUE_CHUNK(CI) do {                                                    \
    const int k0_ = (CI) * 32;                                                  \
    const uint32_t st_ = sbase + ((CI) & 1) * STAGE_BYTES;                      \
    const uint32_t d0 = st_ + crow * SA_BYTES + cu * 16;                        \
    const uint32_t d1 = st_ + (crow + 64) * SA_BYTES + cu * 16;                 \
    const size_t ga = (size_t)(m0 + crow) * 256 + k0_ + cu * 8;                 \
    const size_t gb = (size_t)(n0 + crow) * 256 + k0_ + cu * 8;                 \
    CP_ASYNC16(d0,                      Ah + ga);                               \
    CP_ASYNC16(d1,                      Ah + ga + 64 * 256);                    \
    CP_ASYNC16(d0 + TILE_BYTES,         Al + ga);                               \
    CP_ASYNC16(d1 + TILE_BYTES,         Al + ga + 64 * 256);                    \
    CP_ASYNC16(d0 + 2 * TILE_BYTES,     bhp + gb);                              \
    CP_ASYNC16(d1 + 2 * TILE_BYTES,     bhp + gb + 64 * 256);                   \
    CP_ASYNC16(d0 + 3 * TILE_BYTES,     blp + gb);                              \
    CP_ASYNC16(d1 + 3 * TILE_BYTES,     blp + gb + 64 * 256);                   \
    CP_COMMIT();                                                                \
} while (0)

    ISSUE_CHUNK(0);

#pragma unroll 1
    for (int ci = 0; ci < 8; ci++) {
        if (ci < 7) { ISSUE_CHUNK(ci + 1); CP_WAIT1(); }
        else        { CP_WAIT0(); }
        __syncthreads();

        const uint32_t st = sbase + (ci & 1) * STAGE_BYTES;
#pragma unroll
        for (int kk = 0; kk < 32; kk += 16) {
            uint32_t ah[2][4], al[2][4];
#pragma unroll
            for (int mf = 0; mf < 2; mf++) {
                uint32_t addr = st + (wm + mf * 16 + arow) * SA_BYTES + (kk + acol) * 2;
                LDSM4(ah[mf], addr);
                LDSM4(al[mf], addr + TILE_BYTES);
            }
            uint32_t bhf[8][2], blf[8][2];
#pragma unroll
            for (int np = 0; np < 4; np++) {
                uint32_t addr = st + 2 * TILE_BYTES
                              + (wn + np * 16 + brow) * SA_BYTES + (kk + bcol) * 2;
                uint32_t r[4];
                LDSM4(r, addr);
                bhf[2 * np][0] = r[0]; bhf[2 * np][1] = r[1];
                bhf[2 * np + 1][0] = r[2]; bhf[2 * np + 1][1] = r[3];
                LDSM4(r, addr + TILE_BYTES);
                blf[2 * np][0] = r[0]; blf[2 * np][1] = r[1];
                blf[2 * np + 1][0] = r[2]; blf[2 * np + 1][1] = r[3];
            }
#pragma unroll
            for (int mf = 0; mf < 2; mf++)
#pragma unroll
                for (int nf = 0; nf < 8; nf++) {
                    mma_bf16(c[mf][nf], ah[mf], bhf[nf]);
                    mma_bf16(c[mf][nf], ah[mf], blf[nf]);
                    mma_bf16(c[mf][nf], al[mf], bhf[nf]);
                }
        }
        __syncthreads();
    }

    const int erow = lane >> 2;
    const int ecol = (lane & 3) * 2;

    if (MODE == 0) {
#pragma unroll
        for (int mf = 0; mf < 2; mf++) {
            const int gr0 = m0 + wm + mf * 16 + erow;
#pragma unroll
            for (int nf = 0; nf < 8; nf++) {
                const int gc = n0 + wn + nf * 8 + ecol;
                float2 bb = *(const float2*)&bias[gc];
                float v00 = fmaxf(c[mf][nf][0] + bb.x, 0.f);
                float v01 = fmaxf(c[mf][nf][1] + bb.y, 0.f);
                float v10 = fmaxf(c[mf][nf][2] + bb.x, 0.f);
                float v11 = fmaxf(c[mf][nf][3] + bb.y, 0.f);
                const size_t i0 = (size_t)gr0 * 256 + gc;
                const size_t i1 = (size_t)(gr0 + 8) * 256 + gc;
                uint32_t h0, l0, h1, l1;
                split2(v00, v01, h0, l0);
                split2(v10, v11, h1, l1);
                *(uint32_t*)(oh + i0) = h0;
                *(uint32_t*)(oh + i1) = h1;
                *(uint32_t*)(ol + i0) = l0;
                *(uint32_t*)(ol + i1) = l1;
            }
        }
    } else {
        float part[2][2] = {{0.f, 0.f}, {0.f, 0.f}};
#pragma unroll
        for (int mf = 0; mf < 2; mf++)
#pragma unroll
            for (int nf = 0; nf < 8; nf++) {
                const int lc = wn + nf * 8 + ecol;
                const float b0s = s_bias[lc], b1s = s_bias[lc + 1];
                const float w0 = s_w2[lc], w1 = s_w2[lc + 1];
                part[mf][0] = fmaf(fmaxf(c[mf][nf][0] + b0s, 0.f), w0, part[mf][0]);
                part[mf][0] = fmaf(fmaxf(c[mf][nf][1] + b1s, 0.f), w1, part[mf][0]);
                part[mf][1] = fmaf(fmaxf(c[mf][nf][2] + b0s, 0.f), w0, part[mf][1]);
                part[mf][1] = fmaf(fmaxf(c[mf][nf][3] + b1s, 0.f), w1, part[mf][1]);
            }
#pragma unroll
        for (int mf = 0; mf < 2; mf++)
#pragma unroll
            for (int h = 0; h < 2; h++) {
                part[mf][h] += __shfl_xor_sync(0xffffffffu, part[mf][h], 1);
                part[mf][h] += __shfl_xor_sync(0xffffffffu, part[mf][h], 2);
            }
        if ((lane & 3) == 0) {
#pragma unroll
            for (int mf = 0; mf < 2; mf++)
#pragma unroll
                for (int h = 0; h < 2; h++) {
                    const int row = m0 + wm + mf * 16 + h * 8 + erow;
                    atomicAdd(&yleaf[(size_t)mat * BATCH + row], part[mf][h]);
                }
        }
    }
#undef ISSUE_CHUNK
}

// ---------------------------------------------------------------------------
// Inner-node kernel via mma.sync. Per (m-tile 64 rows, node n):
//  Phase A: H[64,64] = relu(emb@W1t^T + b1)  (K=256, double-buffered cp.async)
//  Phase B: z[64,256] = H@Wwt^T + bw          (K=64)
//  Epilogue: softmax over 256, dot with x, Wb/Wbeta dots, sigmoid -> pR
// ---------------------------------------------------------------------------
#define IN_STAGE_SZ 20480            // Ah 0 | Al 5120 | W1h 10240 | W1l 15360
#define IN_WWH   40960               // 256 x 144B
#define IN_WWL   77824
#define IN_HH    114688              // 64 x 144B
#define IN_HL    123904
#define IN_RED   133120              // redmax[2][64], redse[2][64], redsx[2][64]
#define IN_WBS   134656              // Wb 50 f32
#define IN_WBTS  134856              // Wbeta 50 f32
#define IN_SMEM  135296

__global__ __launch_bounds__(256, 1) void inner_mma_kernel(
    const __nv_bfloat16* __restrict__ eh, const __nv_bfloat16* __restrict__ el,
    const __nv_bfloat16* __restrict__ w1h, const __nv_bfloat16* __restrict__ w1l,
    const __nv_bfloat16* __restrict__ wwh, const __nv_bfloat16* __restrict__ wwl,
    const float* __restrict__ x, const float* __restrict__ b1,
    const float* __restrict__ bw, const float* __restrict__ Wb,
    const float* __restrict__ bb, const float* __restrict__ Wbt,
    const float* __restrict__ bbt, float* __restrict__ pR)
{
    extern __shared__ char smem[];
    const uint32_t sb = smem_u32(smem);
    const int tid = threadIdx.x, lane = tid & 31, w = tid >> 5;
    const int n = blockIdx.y, m0 = blockIdx.x * 64;

    float* sWb  = (float*)(smem + IN_WBS);
    float* sWbt = (float*)(smem + IN_WBTS);
    if (tid < HDIM)                sWb[tid] = Wb[n * HDIM + tid];
    else if (tid < 2 * HDIM)       sWbt[tid - HDIM] = Wbt[n * HDIM + tid - HDIM];

    const int crow = tid >> 2, cu = tid & 3;
    const __nv_bfloat16* w1hp = w1h + (size_t)n * 64 * 256;
    const __nv_bfloat16* w1lp = w1l + (size_t)n * 64 * 256;

#define IN_ISSUE(CI) do {                                           \
    const int k0_ = (CI) * 32;                                      \
    const uint32_t st_ = sb + ((CI) & 1) * IN_STAGE_SZ;             \
    const uint32_t d = st_ + crow * 80 + cu * 16;                   \
    const size_t ga = (size_t)(m0 + crow) * 256 + k0_ + cu * 8;     \
    const size_t gw = (size_t)crow * 256 + k0_ + cu * 8;            \
    CP_ASYNC16(d,         eh + ga);                                 \
    CP_ASYNC16(d + 5120,  el + ga);                                 \
    CP_ASYNC16(d + 10240, w1hp + gw);                               \
    CP_ASYNC16(d + 15360, w1lp + gw);                               \
    CP_COMMIT();                                                    \
} while (0)

    IN_ISSUE(0);
    // Ww prefetch: [256][64] hi/lo, row stride 144B
    {
        const __nv_bfloat16* wh = wwh + (size_t)n * 256 * 64;
        const __nv_bfloat16* wl = wwl + (size_t)n * 256 * 64;
        const int un = tid & 7;
#pragma unroll
        for (int rep = 0; rep < 8; rep++) {
            const int row = (tid >> 3) + rep * 32;
            const uint32_t d = sb + IN_WWH + row * 144 + un * 16;
            const size_t g = (size_t)row * 64 + un * 8;
            CP_ASYNC16(d, wh + g);
            CP_ASYNC16(d + (IN_WWL - IN_WWH), wl + g);
        }
        CP_COMMIT();
    }

    const int arow = (lane & 7) + ((lane >> 3) & 1) * 8;
    const int acol = (lane >> 4) * 8;
    const int brow = (lane & 7) + (lane >> 4) * 8;
    const int bcol = ((lane >> 3) & 1) * 8;

    // ---- Phase A ----
    const int wmA = (w >> 1) * 16, wnA = (w & 1) * 32;
    float accA[4][4];
#pragma unroll
    for (int i = 0; i < 4; i++)
#pragma unroll
        for (int q = 0; q < 4; q++) accA[i][q] = 0.f;

#pragma unroll 1
    for (int ci = 0; ci < 8; ci++) {
        if (ci < 7) IN_ISSUE(ci + 1);
        if (ci == 0)      CP_WAIT2();
        else if (ci < 7)  CP_WAIT1();
        else              CP_WAIT0();
        __syncthreads();

        const uint32_t st = sb + (ci & 1) * IN_STAGE_SZ;
#pragma unroll
        for (int kk = 0; kk < 32; kk += 16) {
            uint32_t ah[4], al[4];
            const uint32_t aaddr = st + (wmA + arow) * 80 + (kk + acol) * 2;
            LDSM4(ah, aaddr);
            LDSM4(al, aaddr + 5120);
            uint32_t bh[4][2], bl[4][2];
#pragma unroll
            for (int g = 0; g < 2; g++) {
                const uint32_t baddr = st + 10240
                    + (wnA + g * 16 + brow) * 80 + (kk + bcol) * 2;
                uint32_t r[4];
                LDSM4(r, baddr);
                bh[2 * g][0] = r[0]; bh[2 * g][1] = r[1];
                bh[2 * g + 1][0] = r[2]; bh[2 * g + 1][1] = r[3];
                LDSM4(r, baddr + 5120);
                bl[2 * g][0] = r[0]; bl[2 * g][1] = r[1];
                bl[2 * g + 1][0] = r[2]; bl[2 * g + 1][1] = r[3];
            }
#pragma unroll
            for (int nf = 0; nf < 4; nf++) {
                mma_bf16(accA[nf], ah, bh[nf]);
                mma_bf16(accA[nf], ah, bl[nf]);
                mma_bf16(accA[nf], al, bh[nf]);
            }
        }
        __syncthreads();
    }
#undef IN_ISSUE

    // Phase A epilogue: relu(+b1), split, store H to smem
    {
        const int r0 = wmA + (lane >> 2);
#pragma unroll
        for (int nf = 0; nf < 4; nf++) {
            const int col = wnA + nf * 8 + (lane & 3) * 2;
            const float bb0 = (col < HDIM)     ? b1[n * HDIM + col]     : 0.f;
            const float bb1 = (col + 1 < HDIM) ? b1[n * HDIM + col + 1] : 0.f;
            float v00 = fmaxf(accA[nf][0] + bb0, 0.f);
            float v01 = fmaxf(accA[nf][1] + bb1, 0.f);
            float v10 = fmaxf(accA[nf][2] + bb0, 0.f);
            float v11 = fmaxf(accA[nf][3] + bb1, 0.f);
            uint32_t h0, l0, h1, l1;
            split2(v00, v01, h0, l0);
            split2(v10, v11, h1, l1);
            *(uint32_t*)(smem + IN_HH + r0 * 144 + col * 2) = h0;
            *(uint32_t*)(smem + IN_HL + r0 * 144 + col * 2) = l0;
            *(uint32_t*)(smem + IN_HH + (r0 + 8) * 144 + col * 2) = h1;
            *(uint32_t*)(smem + IN_HL + (r0 + 8) * 144 + col * 2) = l1;
        }
    }
    __syncthreads();

    // ---- Phase B: z[64,256] = H @ Wwt^T ----
    const int wmB = (w >> 1) * 16, wnB = (w & 1) * 128;
    float z[16][4];
#pragma unroll
    for (int nf = 0; nf < 16; nf++)
#pragma unroll
        for (int q = 0; q < 4; q++) z[nf][q] = 0.f;

#pragma unroll
    for (int kk = 0; kk < 64; kk += 16) {
        uint32_t ah[4], al[4];
        const uint32_t aaddr = sb + IN_HH + (wmB + arow) * 144 + (kk + acol) * 2;
        LDSM4(ah, aaddr);
        LDSM4(al, aaddr + (IN_HL - IN_HH));
#pragma unroll
        for (int g = 0; g < 8; g++) {
            const uint32_t baddr = sb + IN_WWH
                + (wnB + g * 16 + brow) * 144 + (kk + bcol) * 2;
            uint32_t rh[4], rl[4];
            LDSM4(rh, baddr);
            LDSM4(rl, baddr + (IN_WWL - IN_WWH));
            uint32_t b0h[2] = {rh[0], rh[1]}, b1h[2] = {rh[2], rh[3]};
            uint32_t b0l[2] = {rl[0], rl[1]}, b1l[2] = {rl[2], rl[3]};
            mma_bf16(z[2 * g],     ah, b0h);
            mma_bf16(z[2 * g],     ah, b0l);
            mma_bf16(z[2 * g],     al, b0h);
            mma_bf16(z[2 * g + 1], ah, b1h);
            mma_bf16(z[2 * g + 1], ah, b1l);
            mma_bf16(z[2 * g + 1], al, b1h);
        }
    }

    // ---- Phase B epilogue ----
    float* redmax = (float*)(smem + IN_RED);       // [2][64]
    float* redse  = redmax + 128;                  // [2][64]
    float* redsx  = redse + 128;                   // [2][64]

    const int r0 = wmB + (lane >> 2), r1 = r0 + 8;
    float mx0 = -1e30f, mx1 = -1e30f;
#pragma unroll
    for (int nf = 0; nf < 16; nf++) {
        const int col = wnB + nf * 8 + (lane & 3) * 2;
        float2 bwv = *(const float2*)&bw[n * 256 + col];
        z[nf][0] += bwv.x; z[nf][1] += bwv.y;
        z[nf][2] += bwv.x; z[nf][3] += bwv.y;
        mx0 = fmaxf(mx0, fmaxf(z[nf][0], z[nf][1]));
        mx1 = fmaxf(mx1, fmaxf(z[nf][2], z[nf][3]));
    }
    mx0 = fmaxf(mx0, __shfl_xor_sync(0xffffffffu, mx0, 1));
    mx0 = fmaxf(mx0, __shfl_xor_sync(0xffffffffu, mx0, 2));
    mx1 = fmaxf(mx1, __shfl_xor_sync(0xffffffffu, mx1, 1));
    mx1 = fmaxf(mx1, __shfl_xor_sync(0xffffffffu, mx1, 2));
    if ((lane & 3) == 0) {
        redmax[(w & 1) * 64 + r0] = mx0;
        redmax[(w & 1) * 64 + r1] = mx1;
    }
    __syncthreads();
    mx0 = fmaxf(redmax[r0], redmax[64 + r0]);
    mx1 = fmaxf(redmax[r1], redmax[64 + r1]);

    float se0 = 0.f, sx0 = 0.f, se1 = 0.f, sx1 = 0.f;
    const float* x0 = x + (size_t)(m0 + r0) * 256;
    const float* x1 = x + (size_t)(m0 + r1) * 256;
#pragma unroll
    for (int nf = 0; nf < 16; nf++) {
        const int col = wnB + nf * 8 + (lane & 3) * 2;
        float2 xv0 = *(const float2*)&x0[col];
        float2 xv1 = *(const float2*)&x1[col];
        float e;
        e = __expf(z[nf][0] - mx0); se0 += e; sx0 = fmaf(e, xv0.x, sx0);
        e = __expf(z[nf][1] - mx0); se0 += e; sx0 = fmaf(e, xv0.y, sx0);
        e = __expf(z[nf][2] - mx1); se1 += e; sx1 = fmaf(e, xv1.x, sx1);
        e = __expf(z[nf][3] - mx1); se1 += e; sx1 = fmaf(e, xv1.y, sx1);
    }
#pragma unroll
    for (int off = 1; off <= 2; off <<= 1) {
        se0 += __shfl_xor_sync(0xffffffffu, se0, off);
        sx0 += __shfl_xor_sync(0xffffffffu, sx0, off);
        se1 += __shfl_xor_sync(0xffffffffu, se1, off);
        sx1 += __shfl_xor_sync(0xffffffffu, sx1, off);
    }
    if ((lane & 3) == 0) {
        redse[(w & 1) * 64 + r0] = se0; redse[(w & 1) * 64 + r1] = se1;
        redsx[(w & 1) * 64 + r0] = sx0; redsx[(w & 1) * 64 + r1] = sx1;
    }
    __syncthreads();

    if ((w & 1) == 0) {
        float pb0 = 0.f, pbt0 = 0.f, pb1 = 0.f, pbt1 = 0.f;
        for (int j = (lane & 3); j < HDIM; j += 4) {
            float h0 = __bfloat162float(*(const __nv_bfloat16*)(smem + IN_HH + r0 * 144 + j * 2))
                     + __bfloat162float(*(const __nv_bfloat16*)(smem + IN_HL + r0 * 144 + j * 2));
            float h1 = __bfloat162float(*(const __nv_bfloat16*)(smem + IN_HH + r1 * 144 + j * 2))
                     + __bfloat162float(*(const __nv_bfloat16*)(smem + IN_HL + r1 * 144 + j * 2));
            pb0  = fmaf(h0, sWb[j],  pb0);
            pbt0 = fmaf(h0, sWbt[j], pbt0);
            pb1  = fmaf(h1, sWb[j],  pb1);
            pbt1 = fmaf(h1, sWbt[j], pbt1);
        }
#pragma unroll
        for (int off = 1; off <= 2; off <<= 1) {
            pb0  += __shfl_xor_sync(0xffffffffu, pb0, off);
            pbt0 += __shfl_xor_sync(0xffffffffu, pbt0, off);
            pb1  += __shfl_xor_sync(0xffffffffu, pb1, off);
            pbt1 += __shfl_xor_sync(0xffffffffu, pbt1, off);
        }
        if ((lane & 3) == 0) {
            const float bbn = bb[n], bbtn = bbt[n];
            float seA = redse[r0] + redse[64 + r0];
            float sxA = redsx[r0] + redsx[64 + r0];
            float val = (pbt0 + bbtn) * (sxA / seA + pb0 + bbn);
            pR[(size_t)n * BATCH + m0 + r0] = 1.f / (1.f + __expf(-val));
            seA = redse[r1] + redse[64 + r1];
            sxA = redsx[r1] + redsx[64 + r1];
            val = (pbt1 + bbtn) * (sxA / seA + pb1 + bbn);
            pR[(size_t)n * BATCH + m0 + r1] = 1.f / (1.f + __expf(-val));
        }
    }
}

// ---------------------------------------------------------------------------
// Combine: out[b] = sum_leaf prob(leaf,b) * (y_leaf[leaf,b] + b2[leaf])
// ---------------------------------------------------------------------------
__global__ __launch_bounds__(256) void combine_kernel(
    const float* __restrict__ pR, const float* __restrict__ yl,
    const float* __restrict__ b2, float* __restrict__ out)
{
    const int b = blockIdx.x * 256 + threadIdx.x;
    float p[N_INNER];
#pragma unroll
    for (int i = 0; i < N_INNER; i++) p[i] = pR[(size_t)i * BATCH + b];

    float prob[N_LEAF];
    prob[0] = 1.f;
#pragma unroll
    for (int lev = 0; lev < 5; lev++) {
        const int cnt = 1 << lev;
        const int off = cnt - 1;
#pragma unroll
        for (int i = N_LEAF - 1; i >= 0; i--) {
            if (i < cnt) {
                float pr   = p[off + i];
                float base = prob[i];
                prob[2 * i]     = base * (1.f - pr);
                prob[2 * i + 1] = base * pr;
            }
        }
    }
    float acc = 0.f;
#pragma unroll
    for (int l = 0; l < N_LEAF; l++)
        acc = fmaf(prob[l], yl[(size_t)l * BATCH + b] + b2[l], acc);
    out[b] = acc;
}

// ---------------------------------------------------------------------------
extern "C" void kernel_launch(void* const* d_in, const int* in_sizes, int n_in,
                              void* d_out, int out_size)
{
    const float* x       = (const float*)d_in[0];
    const float* enc_W   = (const float*)d_in[1];
    const float* enc_b   = (const float*)d_in[2];
    const float* in_W1   = (const float*)d_in[3];
    const float* in_b1   = (const float*)d_in[4];
    const float* in_Ww   = (const float*)d_in[5];
    const float* in_bw   = (const float*)d_in[6];
    const float* in_Wb   = (const float*)d_in[7];
    const float* in_bb   = (const float*)d_in[8];
    const float* in_Wbt  = (const float*)d_in[9];
    const float* in_bbt  = (const float*)d_in[10];
    const float* lf_W1   = (const float*)d_in[11];
    const float* lf_b1   = (const float*)d_in[12];
    const float* lf_W2   = (const float*)d_in[13];
    const float* lf_b2   = (const float*)d_in[14];
    float* out = (float*)d_out;

    float *pR, *yl;
    __nv_bfloat16 *xh, *xl, *e0h, *e0l, *e1h, *e1l, *wth, *wtl;
    __nv_bfloat16 *w1th, *w1tl, *wwth, *wwtl;
    cudaGetSymbolAddress((void**)&pR,  g_pR);
    cudaGetSymbolAddress((void**)&yl,  g_yleaf);
    cudaGetSymbolAddress((void**)&xh,  g_xh);
    cudaGetSymbolAddress((void**)&xl,  g_xl);
    cudaGetSymbolAddress((void**)&e0h, g_e0h);
    cudaGetSymbolAddress((void**)&e0l, g_e0l);
    cudaGetSymbolAddress((void**)&e1h, g_e1h);
    cudaGetSymbolAddress((void**)&e1l, g_e1l);
    cudaGetSymbolAddress((void**)&wth, g_wth);
    cudaGetSymbolAddress((void**)&wtl, g_wtl);
    cudaGetSymbolAddress((void**)&w1th, g_w1th);
    cudaGetSymbolAddress((void**)&w1tl, g_w1tl);
    cudaGetSymbolAddress((void**)&wwth, g_wwth);
    cudaGetSymbolAddress((void**)&wwtl, g_wwtl);

    cudaFuncSetAttribute(mm_kernel<0>, cudaFuncAttributeMaxDynamicSharedMemorySize, MM_SMEM);
    cudaFuncSetAttribute(mm_kernel<1>, cudaFuncAttributeMaxDynamicSharedMemorySize, MM_SMEM);
    cudaFuncSetAttribute(inner_mma_kernel, cudaFuncAttributeMaxDynamicSharedMemorySize, IN_SMEM);

    // --- prep ---
    prep_x_kernel<<<BATCH * EDIM / 1024, 256>>>(x, xh, xl);
    prep_w_kernel<<<dim3(8, 8, 4),  dim3(32, 8)>>>(enc_W, wth, wtl);
    prep_w_kernel<<<dim3(8, 8, 32), dim3(32, 8)>>>(lf_W1, wth + 4 * 65536, wtl + 4 * 65536);
    prep_w1_kernel<<<N_INNER * 64, 256>>>(in_W1, w1th, w1tl);
    prep_ww_kernel<<<N_INNER * 64, 256>>>(in_Ww, wwth, wwtl);
    zero_kernel<<<N_LEAF * BATCH / 1024, 256>>>(yl);

    // --- encoder: 4 layers ---
    mm_kernel<0><<<dim3(64, 2), 256, MM_SMEM>>>(xh, xl, wth, wtl,
        enc_b, nullptr, e0h, e0l, nullptr);
    mm_kernel<0><<<dim3(64, 2), 256, MM_SMEM>>>(e0h, e0l, wth + 65536, wtl + 65536,
        enc_b + 256, nullptr, e1h, e1l, nullptr);
    mm_kernel<0><<<dim3(64, 2), 256, MM_SMEM>>>(e1h, e1l, wth + 2 * 65536, wtl + 2 * 65536,
        enc_b + 512, nullptr, e0h, e0l, nullptr);
    mm_kernel<0><<<dim3(64, 2), 256, MM_SMEM>>>(e0h, e0l, wth + 3 * 65536, wtl + 3 * 65536,
        enc_b + 768, nullptr, e1h, e1l, nullptr);

    // --- inner gates (mma.sync) ---
    inner_mma_kernel<<<dim3(BATCH / 64, N_INNER), 256, IN_SMEM>>>(
        e1h, e1l, w1th, w1tl, wwth, wwtl,
        x, in_b1, in_bw, in_Wb, in_bb, in_Wbt, in_bbt, pR);

    // --- leaves (mma.sync, atomicAdd into yl) ---
    mm_kernel<1><<<dim3(64, 2, N_LEAF), 256, MM_SMEM>>>(
        e1h, e1l, wth + 4 * 65536, wtl + 4 * 65536,
        lf_b1, lf_W2, nullptr, nullptr, yl);

    // --- combine ---
    combine_kernel<<<BATCH / 256, 256>>>(pR, yl, lf_b2, out);
}